// round 5
// baseline (speedup 1.0000x reference)
#include <cuda_runtime.h>
#include <cuda_bf16.h>

#define NB 16
#define NE 2048
#define NP 16384
#define NL 5
#define ND 64

// Scratch: per-(b,e,l) dot products, 16*2048*5 floats = 640 KB
__device__ __align__(16) float g_dot[NB * NE * NL];
__device__ int g_is64;

// ---------------------------------------------------------------------------
// Kernel 1: dot[b,e,l] = sum_d emb[b,e,d] * ev[l,d]
// 4 lanes per row, each lane holds 16 floats (4x float4); 8 rows per warp.
// Per l: 16 FMAs + 2-step butterfly over the 4-lane group.
// Lane sub keeps l=sub; lane 0 additionally keeps l=4.
// Block 0 also sniffs the paths dtype (int64 -> odd 32-bit words are 0/-1).
// ---------------------------------------------------------------------------
__global__ __launch_bounds__(256) void dot_kernel(
    const float* __restrict__ emb, const float* __restrict__ ev,
    const int* __restrict__ pathw) {

    if (blockIdx.x == 0) {
        int bad = 0;
        #pragma unroll 4
        for (int i = threadIdx.x; i < 4096; i += 256) {
            int w = __ldg(pathw + 2 * i + 1);
            bad |= (w != 0 && w != -1);
        }
        bad = __syncthreads_or(bad);
        if (threadIdx.x == 0) g_is64 = bad ? 0 : 1;
    }

    int warp = threadIdx.x >> 5;
    int lane = threadIdx.x & 31;
    int grp  = lane >> 2;          // 8 rows per warp
    int sub  = lane & 3;           // 4 lanes per row
    int row  = blockIdx.x * 64 + warp * 8 + grp;   // (b*E + e)

    const float4* rp = reinterpret_cast<const float4*>(emb) + (size_t)row * (ND / 4);
    float4 v[4];
    #pragma unroll
    for (int k = 0; k < 4; k++) v[k] = rp[4 * k + sub];

    const float4* ev4 = reinterpret_cast<const float4*>(ev);
    float res = 0.f, res4 = 0.f;
    #pragma unroll
    for (int l = 0; l < NL; l++) {
        float s = 0.f;
        #pragma unroll
        for (int k = 0; k < 4; k++) {
            float4 e = __ldg(&ev4[l * (ND / 4) + 4 * k + sub]);
            s += v[k].x * e.x + v[k].y * e.y + v[k].z * e.z + v[k].w * e.w;
        }
        s += __shfl_xor_sync(0xffffffffu, s, 1);
        s += __shfl_xor_sync(0xffffffffu, s, 2);
        if (l < 4) { if (sub == l) res = s; }
        else       { res4 = s; }
    }
    g_dot[row * NL + sub] = res;
    if (sub == 0) g_dot[row * NL + 4] = res4;
}

// ---------------------------------------------------------------------------
// Kernel 2: enc[b,p] = (sum_l valid ? dot[b, idx, l] : 0) * recip[count]
// 256 threads, 1024 p per block -> grid (16, 16). smem = 40KB table + 20KB
// compacted path words (low 32 bits only; valid for int64 and int32:
// low word of -1 is -1, valid ids < 2^31) -> 60KB => 3 blocks/SM.
// Gather: addr word = lane*5 + l, gcd(5,32)=1 -> bank-conflict-free.
// ---------------------------------------------------------------------------
#define ETH 256
#define EPPT 4
#define PBLK (ETH * EPPT)                       // 1024 paths per block
#define ENC_SMEM (NE * NL * 4 + PBLK * NL * 4)  // 40960 + 20480 = 61440 B

__constant__ float c_recip[8] = {
    0.f,                       // cnt=0: acc is 0; 0 matches 0/(0+eps)
    1.0f / (1.0f + 1e-9f),
    1.0f / (2.0f + 1e-9f),
    1.0f / (3.0f + 1e-9f),
    1.0f / (4.0f + 1e-9f),
    1.0f / (5.0f + 1e-9f),
    0.f, 0.f
};

__global__ __launch_bounds__(ETH) void enc_kernel(
    const void* __restrict__ paths, float* __restrict__ out) {
    extern __shared__ unsigned char smem[];
    float* tab = reinterpret_cast<float*>(smem);          // NE*NL floats
    int*   sp  = reinterpret_cast<int*>(smem + NE * NL * 4);  // PBLK*NL words

    const int b  = blockIdx.y;
    const int p0 = blockIdx.x * PBLK;
    const bool is64 = (g_is64 != 0);

    // Stage this block's path chunk first (DRAM latency), compacted to low words.
    if (is64) {
        const int4* psrc = reinterpret_cast<const int4*>(
            (const unsigned char*)paths + ((size_t)b * NP + p0) * NL * 8);
        int2* pdst = reinterpret_cast<int2*>(sp);
        #pragma unroll
        for (int i = threadIdx.x; i < PBLK * NL / 2; i += ETH) {  // 2560 int4
            int4 v = __ldg(psrc + i);
            pdst[i] = make_int2(v.x, v.z);
        }
    } else {
        const int4* psrc = reinterpret_cast<const int4*>(
            (const unsigned char*)paths + ((size_t)b * NP + p0) * NL * 4);
        int4* pdst = reinterpret_cast<int4*>(sp);
        #pragma unroll
        for (int i = threadIdx.x; i < PBLK * NL / 4; i += ETH)    // 1280 int4
            pdst[i] = __ldg(psrc + i);
    }
    // Stage the batch's dot table (L2-resident source).
    {
        const float4* src = reinterpret_cast<const float4*>(g_dot + (size_t)b * NE * NL);
        float4* dst = reinterpret_cast<float4*>(tab);
        #pragma unroll
        for (int i = threadIdx.x; i < (NE * NL) / 4; i += ETH)    // 2560 float4
            dst[i] = __ldg(src + i);
    }
    __syncthreads();

    #pragma unroll
    for (int it = 0; it < EPPT; it++) {
        int lp = it * ETH + threadIdx.x;        // local p in [0, PBLK)
        const int* q = sp + lp * NL;
        float acc = 0.f;
        int cnt = 0;
        #pragma unroll
        for (int l = 0; l < NL; l++) {
            int idx = q[l];
            if (idx >= 0) { acc += tab[idx * NL + l]; cnt++; }
        }
        out[(size_t)b * NP + p0 + lp] = acc * c_recip[cnt];
    }
}

// ---------------------------------------------------------------------------
extern "C" void kernel_launch(void* const* d_in, const int* in_sizes, int n_in,
                              void* d_out, int out_size) {
    const float* emb   = (const float*)d_in[0];  // (B, E, D) float32
    const void*  paths = d_in[1];                // (B, P, L) int64 or int32
    const float* ev    = (const float*)d_in[2];  // (L, D) float32
    float* out = (float*)d_out;                  // (B, P) float32

    // 32768 rows, 64 rows/block
    dot_kernel<<<NB * NE / 64, 256>>>(emb, ev, (const int*)paths);

    cudaFuncSetAttribute(enc_kernel, cudaFuncAttributeMaxDynamicSharedMemorySize,
                         ENC_SMEM);
    dim3 grid(NP / PBLK, NB);                 // (16, 16)
    enc_kernel<<<grid, ETH, ENC_SMEM>>>(paths, out);
}

// round 6
// speedup vs baseline: 1.1834x; 1.1834x over previous
#include <cuda_runtime.h>
#include <cuda_bf16.h>

#define NB 16
#define NE 2048
#define NP 16384
#define NL 5
#define ND 64

// Scratch: per-(b,e,l) dot products, 16*2048*5 floats = 640 KB
__device__ __align__(16) float g_dot[NB * NE * NL];
__device__ int g_is64;

// ---------------------------------------------------------------------------
// Kernel 1: dot[b,e,l] = sum_d emb[b,e,d] * ev[l,d]
// 8 lanes per row (each lane: 8 floats via 2x float4, fully coalesced);
// 4 rows per warp. Per l: 8 FMAs then 3-step butterfly over the 8-lane group.
// (R4 version — 262K threads, measured ~3.9us.)
// Block 0 also sniffs the paths dtype (int64 -> odd 32-bit words are 0/-1).
// ---------------------------------------------------------------------------
__global__ __launch_bounds__(256) void dot_kernel(
    const float* __restrict__ emb, const float* __restrict__ ev,
    const int* __restrict__ pathw) {

    if (blockIdx.x == 0) {
        int bad = 0;
        #pragma unroll 4
        for (int i = threadIdx.x; i < 4096; i += 256) {
            int w = __ldg(pathw + 2 * i + 1);
            bad |= (w != 0 && w != -1);
        }
        bad = __syncthreads_or(bad);
        if (threadIdx.x == 0) g_is64 = bad ? 0 : 1;
    }

    int warp = threadIdx.x >> 5;
    int lane = threadIdx.x & 31;
    int grp  = lane >> 3;          // 4 rows per warp
    int sub  = lane & 7;           // 8 lanes per row
    int row  = blockIdx.x * 32 + warp * 4 + grp;   // (b*E + e)

    const float4* rp = reinterpret_cast<const float4*>(emb) + (size_t)row * (ND / 4);
    float4 v0 = rp[sub];           // d in [sub*4, sub*4+4)
    float4 v1 = rp[sub + 8];       // d in [32+sub*4, ...)

    const float4* ev4 = reinterpret_cast<const float4*>(ev);
    float res = 0.f;
    #pragma unroll
    for (int l = 0; l < NL; l++) {
        float4 e0 = ev4[l * (ND / 4) + sub];
        float4 e1 = ev4[l * (ND / 4) + 8 + sub];
        float s = v0.x * e0.x + v0.y * e0.y + v0.z * e0.z + v0.w * e0.w
                + v1.x * e1.x + v1.y * e1.y + v1.z * e1.z + v1.w * e1.w;
        s += __shfl_xor_sync(0xffffffffu, s, 1);
        s += __shfl_xor_sync(0xffffffffu, s, 2);
        s += __shfl_xor_sync(0xffffffffu, s, 4);
        if (sub == l) res = s;
    }
    if (sub < NL) g_dot[row * NL + sub] = res;
}

// ---------------------------------------------------------------------------
// Kernel 2: enc[b,p] = (sum_l valid ? dot[b, idx, l] : 0) * recip[count]
// 512 threads, 512 p per block -> grid (32, 16) = 512 blocks.
// smem = 40KB tab + 10KB compacted path words = 50KB -> 4 blocks/SM allowed,
// grid supplies ~3.5/SM -> ~86% occupancy (vs 40% at grid 256).
// Path words compacted to low 32 bits (valid for int64 and int32: low word
// of -1 is -1, valid ids < 2^31). Gather addr = p*5 + l, gcd(5,32)=1 ->
// bank-conflict-free.
// ---------------------------------------------------------------------------
#define ETH 512
#define PBLK 512
#define ENC_SMEM (NE * NL * 4 + PBLK * NL * 4)  // 40960 + 10240 = 51200 B

__constant__ float c_recip[8] = {
    0.f,                       // cnt=0: acc is 0; 0 matches 0/(0+eps)
    1.0f / (1.0f + 1e-9f),
    1.0f / (2.0f + 1e-9f),
    1.0f / (3.0f + 1e-9f),
    1.0f / (4.0f + 1e-9f),
    1.0f / (5.0f + 1e-9f),
    0.f, 0.f
};

__global__ __launch_bounds__(ETH) void enc_kernel(
    const void* __restrict__ paths, float* __restrict__ out) {
    extern __shared__ unsigned char smem[];
    float* tab = reinterpret_cast<float*>(smem);              // NE*NL floats
    int*   sp  = reinterpret_cast<int*>(smem + NE * NL * 4);  // PBLK*NL words

    const int b  = blockIdx.y;
    const int p0 = blockIdx.x * PBLK;
    const bool is64 = (g_is64 != 0);

    // Stage this block's path chunk first (DRAM latency), compacted to low words.
    if (is64) {
        const int4* psrc = reinterpret_cast<const int4*>(
            (const unsigned char*)paths + ((size_t)b * NP + p0) * NL * 8);
        int2* pdst = reinterpret_cast<int2*>(sp);
        #pragma unroll
        for (int i = threadIdx.x; i < PBLK * NL / 2; i += ETH) {  // 1280 int4
            int4 v = __ldg(psrc + i);
            pdst[i] = make_int2(v.x, v.z);
        }
    } else {
        const int4* psrc = reinterpret_cast<const int4*>(
            (const unsigned char*)paths + ((size_t)b * NP + p0) * NL * 4);
        int4* pdst = reinterpret_cast<int4*>(sp);
        #pragma unroll
        for (int i = threadIdx.x; i < PBLK * NL / 4; i += ETH)    // 640 int4
            pdst[i] = __ldg(psrc + i);
    }
    // Stage the batch's dot table (L2-resident source).
    {
        const float4* src = reinterpret_cast<const float4*>(g_dot + (size_t)b * NE * NL);
        float4* dst = reinterpret_cast<float4*>(tab);
        #pragma unroll
        for (int i = threadIdx.x; i < (NE * NL) / 4; i += ETH)    // 2560 float4
            dst[i] = __ldg(src + i);
    }
    __syncthreads();

    {
        int lp = threadIdx.x;                   // local p in [0, PBLK)
        const int* q = sp + lp * NL;
        float acc = 0.f;
        int cnt = 0;
        #pragma unroll
        for (int l = 0; l < NL; l++) {
            int idx = q[l];
            if (idx >= 0) { acc += tab[idx * NL + l]; cnt++; }
        }
        out[(size_t)b * NP + p0 + lp] = acc * c_recip[cnt];
    }
}

// ---------------------------------------------------------------------------
extern "C" void kernel_launch(void* const* d_in, const int* in_sizes, int n_in,
                              void* d_out, int out_size) {
    const float* emb   = (const float*)d_in[0];  // (B, E, D) float32
    const void*  paths = d_in[1];                // (B, P, L) int64 or int32
    const float* ev    = (const float*)d_in[2];  // (L, D) float32
    float* out = (float*)d_out;                  // (B, P) float32

    // 32768 rows, 32 rows/block
    dot_kernel<<<NB * NE / 32, 256>>>(emb, ev, (const int*)paths);

    cudaFuncSetAttribute(enc_kernel, cudaFuncAttributeMaxDynamicSharedMemorySize,
                         ENC_SMEM);
    dim3 grid(NP / PBLK, NB);                 // (32, 16)
    enc_kernel<<<grid, ETH, ENC_SMEM>>>(paths, out);
}

// round 7
// speedup vs baseline: 1.3573x; 1.1470x over previous
#include <cuda_runtime.h>
#include <cuda_bf16.h>

#define NB 16
#define NE 2048
#define NP 16384
#define NL 5
#define ND 64

// Scratch: per-(b,e,l) dot products, 16*2048*5 floats = 640 KB
__device__ __align__(16) float g_dot[NB * NE * NL];
__device__ int g_is64;

// ---------------------------------------------------------------------------
// Kernel 1: dot[b,e,l] = sum_d emb[b,e,d] * ev[l,d]
// 8 lanes per row (each lane: 8 floats via 2x float4, fully coalesced);
// 4 rows per warp. Per l: 8 FMAs then 3-step butterfly over the 8-lane group.
// (proven R4 shape)
// Block 0 also sniffs the paths dtype (int64 -> odd 32-bit words are 0/-1).
// ---------------------------------------------------------------------------
__global__ __launch_bounds__(256) void dot_kernel(
    const float* __restrict__ emb, const float* __restrict__ ev,
    const int* __restrict__ pathw) {

    if (blockIdx.x == 0) {
        int bad = 0;
        #pragma unroll 4
        for (int i = threadIdx.x; i < 4096; i += 256) {
            int w = __ldg(pathw + 2 * i + 1);
            bad |= (w != 0 && w != -1);
        }
        bad = __syncthreads_or(bad);
        if (threadIdx.x == 0) g_is64 = bad ? 0 : 1;
    }

    int warp = threadIdx.x >> 5;
    int lane = threadIdx.x & 31;
    int grp  = lane >> 3;          // 4 rows per warp
    int sub  = lane & 7;           // 8 lanes per row
    int row  = blockIdx.x * 32 + warp * 4 + grp;   // (b*E + e)

    const float4* rp = reinterpret_cast<const float4*>(emb) + (size_t)row * (ND / 4);
    float4 v0 = rp[sub];           // d in [sub*4, sub*4+4)
    float4 v1 = rp[sub + 8];       // d in [32+sub*4, ...)

    const float4* ev4 = reinterpret_cast<const float4*>(ev);
    float res = 0.f;
    #pragma unroll
    for (int l = 0; l < NL; l++) {
        float4 e0 = ev4[l * (ND / 4) + sub];
        float4 e1 = ev4[l * (ND / 4) + 8 + sub];
        float s = v0.x * e0.x + v0.y * e0.y + v0.z * e0.z + v0.w * e0.w
                + v1.x * e1.x + v1.y * e1.y + v1.z * e1.z + v1.w * e1.w;
        s += __shfl_xor_sync(0xffffffffu, s, 1);
        s += __shfl_xor_sync(0xffffffffu, s, 2);
        s += __shfl_xor_sync(0xffffffffu, s, 4);
        if (sub == l) res = s;
    }
    if (sub < NL) g_dot[row * NL + sub] = res;
}

// ---------------------------------------------------------------------------
// Kernel 2: enc[b,p] = (sum_l valid ? dot[b, idx, l] : 0) * recip[count]
// 1024 threads, 1024 p per block -> grid (16, 16) = 256 blocks.
//   * staging amortization of R4 (10 MB table traffic: 256 blocks x 40 KB)
//   * occupancy of R6     (1.73 blocks x 1024 thr ~ 1770 thr/SM, ~86%)
// smem = 40KB tab + 20KB compacted path words + recip = ~60KB.
// Path words compacted to low 32 bits (valid for int64 and int32: low word
// of -1 is -1, valid ids < 2^31). Gather addr = p*5 + l, gcd(5,32)=1 ->
// bank-conflict-free. Recip table lives in smem (banks 0..5, no LDC replays).
// ---------------------------------------------------------------------------
#define ETH 1024
#define PBLK 1024
#define ENC_SMEM (NE * NL * 4 + PBLK * NL * 4 + 32)  // 40960+20480+32 = 61472

__global__ __launch_bounds__(ETH) void enc_kernel(
    const void* __restrict__ paths, float* __restrict__ out) {
    extern __shared__ unsigned char smem[];
    float* tab   = reinterpret_cast<float*>(smem);                  // NE*NL floats
    int*   sp    = reinterpret_cast<int*>(smem + NE * NL * 4);      // PBLK*NL words
    float* recip = reinterpret_cast<float*>(smem + NE * NL * 4 + PBLK * NL * 4);

    if (threadIdx.x < 8) {
        // cnt=0: acc is 0; 0 matches 0/(0+eps)
        recip[threadIdx.x] = (threadIdx.x >= 1 && threadIdx.x <= 5)
                           ? 1.0f / ((float)threadIdx.x + 1e-9f) : 0.f;
    }

    const int b  = blockIdx.y;
    const int p0 = blockIdx.x * PBLK;
    const bool is64 = (g_is64 != 0);

    // Stage this block's path chunk first (longest latency), compacted to low words.
    if (is64) {
        const int4* psrc = reinterpret_cast<const int4*>(
            (const unsigned char*)paths + ((size_t)b * NP + p0) * NL * 8);
        int2* pdst = reinterpret_cast<int2*>(sp);
        #pragma unroll
        for (int i = threadIdx.x; i < PBLK * NL / 2; i += ETH) {  // 2560 int4
            int4 v = __ldg(psrc + i);
            pdst[i] = make_int2(v.x, v.z);
        }
    } else {
        const int4* psrc = reinterpret_cast<const int4*>(
            (const unsigned char*)paths + ((size_t)b * NP + p0) * NL * 4);
        int4* pdst = reinterpret_cast<int4*>(sp);
        #pragma unroll
        for (int i = threadIdx.x; i < PBLK * NL / 4; i += ETH)    // 1280 int4
            pdst[i] = __ldg(psrc + i);
    }
    // Stage the batch's dot table (L2-resident source).
    {
        const float4* src = reinterpret_cast<const float4*>(g_dot + (size_t)b * NE * NL);
        float4* dst = reinterpret_cast<float4*>(tab);
        #pragma unroll
        for (int i = threadIdx.x; i < (NE * NL) / 4; i += ETH)    // 2560 float4
            dst[i] = __ldg(src + i);
    }
    __syncthreads();

    {
        const int lp = threadIdx.x;                 // local p in [0, PBLK)
        const int* q = sp + lp * NL;
        float acc = 0.f;
        int cnt = 0;
        #pragma unroll
        for (int l = 0; l < NL; l++) {
            int idx = q[l];
            if (idx >= 0) { acc += tab[idx * NL + l]; cnt++; }
        }
        out[(size_t)b * NP + p0 + lp] = acc * recip[cnt];
    }
}

// ---------------------------------------------------------------------------
extern "C" void kernel_launch(void* const* d_in, const int* in_sizes, int n_in,
                              void* d_out, int out_size) {
    const float* emb   = (const float*)d_in[0];  // (B, E, D) float32
    const void*  paths = d_in[1];                // (B, P, L) int64 or int32
    const float* ev    = (const float*)d_in[2];  // (L, D) float32
    float* out = (float*)d_out;                  // (B, P) float32

    // 32768 rows, 32 rows/block
    dot_kernel<<<NB * NE / 32, 256>>>(emb, ev, (const int*)paths);

    cudaFuncSetAttribute(enc_kernel, cudaFuncAttributeMaxDynamicSharedMemorySize,
                         ENC_SMEM);
    dim3 grid(NP / PBLK, NB);                 // (16, 16)
    enc_kernel<<<grid, ETH, ENC_SMEM>>>(paths, out);
}

// round 8
// speedup vs baseline: 1.4018x; 1.0327x over previous
#include <cuda_runtime.h>
#include <cuda_bf16.h>

#define NB 16
#define NE 2048
#define NP 16384
#define NL 5
#define ND 64

// Scratch: per-(b,e,l) dot products, 16*2048*5 floats = 640 KB
__device__ __align__(16) float g_dot[NB * NE * NL];
__device__ int g_is64;

// ---------------------------------------------------------------------------
// Kernel 1: dot[b,e,l] = sum_d emb[b,e,d] * ev[l,d]
// 8 lanes per row (2x float4 per lane, fully coalesced); 4 rows per warp.
// Per l: 8 FMAs then 3-step butterfly over the 8-lane group. (proven R4 shape)
// Block 0 also sniffs the paths dtype (int64 -> odd 32-bit words are 0/-1).
// ---------------------------------------------------------------------------
__global__ __launch_bounds__(256) void dot_kernel(
    const float* __restrict__ emb, const float* __restrict__ ev,
    const int* __restrict__ pathw) {

    if (blockIdx.x == 0) {
        int bad = 0;
        #pragma unroll 4
        for (int i = threadIdx.x; i < 4096; i += 256) {
            int w = __ldg(pathw + 2 * i + 1);
            bad |= (w != 0 && w != -1);
        }
        bad = __syncthreads_or(bad);
        if (threadIdx.x == 0) g_is64 = bad ? 0 : 1;
    }

    int warp = threadIdx.x >> 5;
    int lane = threadIdx.x & 31;
    int grp  = lane >> 3;          // 4 rows per warp
    int sub  = lane & 7;           // 8 lanes per row
    int row  = blockIdx.x * 32 + warp * 4 + grp;   // (b*E + e)

    const float4* rp = reinterpret_cast<const float4*>(emb) + (size_t)row * (ND / 4);
    float4 v0 = rp[sub];
    float4 v1 = rp[sub + 8];

    const float4* ev4 = reinterpret_cast<const float4*>(ev);
    float res = 0.f;
    #pragma unroll
    for (int l = 0; l < NL; l++) {
        float4 e0 = ev4[l * (ND / 4) + sub];
        float4 e1 = ev4[l * (ND / 4) + 8 + sub];
        float s = v0.x * e0.x + v0.y * e0.y + v0.z * e0.z + v0.w * e0.w
                + v1.x * e1.x + v1.y * e1.y + v1.z * e1.z + v1.w * e1.w;
        s += __shfl_xor_sync(0xffffffffu, s, 1);
        s += __shfl_xor_sync(0xffffffffu, s, 2);
        s += __shfl_xor_sync(0xffffffffu, s, 4);
        if (sub == l) res = s;
    }
    if (sub < NL) g_dot[row * NL + sub] = res;
}

// ---------------------------------------------------------------------------
// Kernel 2: enc[b,p] = (sum_l valid ? dot[b, idx, l] : 0) * recip[count]
// SINGLE WAVE: grid (8,16) = 128 blocks <= 148 SMs, 1024 threads, 2048 p/blk.
// Paths go straight to REGISTERS (10 independent loads/thread, issued before
// the tab staging loop so DRAM latency hides under the L2 tab stage + barrier).
// smem = 40KB table + recip only. Low 32-bit path words suffice for both
// int32 and int64 (low word of -1 is -1; valid ids < 2^31).
// ---------------------------------------------------------------------------
#define ETH 1024
#define EBX 8
#define PBLK (NP / EBX)          // 2048
#define EPPT (PBLK / ETH)        // 2
#define ENC_SMEM (NE * NL * 4 + 32)   // 40992 B

__global__ __launch_bounds__(ETH) void enc_kernel(
    const void* __restrict__ paths, float* __restrict__ out) {
    extern __shared__ float tab[];            // NE*NL floats + 8 recip
    float* recip = tab + NE * NL;

    if (threadIdx.x < 8) {
        // cnt=0: acc is 0; 0 matches 0/(0+eps)
        recip[threadIdx.x] = (threadIdx.x >= 1 && threadIdx.x <= 5)
                           ? 1.0f / ((float)threadIdx.x + 1e-9f) : 0.f;
    }

    const int b  = blockIdx.y;
    const int p0 = blockIdx.x * PBLK;
    const bool is64 = (g_is64 != 0);   // uniform across grid

    // --- Phase A: issue path loads into registers (longest-latency first) ---
    int w[EPPT][NL];
    if (is64) {
        const int2* src = reinterpret_cast<const int2*>(
            (const unsigned char*)paths + ((size_t)b * NP + p0) * NL * 8);
        #pragma unroll
        for (int it = 0; it < EPPT; it++) {
            const int2* q = src + (it * ETH + threadIdx.x) * NL;
            #pragma unroll
            for (int l = 0; l < NL; l++) w[it][l] = __ldg(q + l).x;
        }
    } else {
        const int* src = reinterpret_cast<const int*>(paths)
                       + ((size_t)b * NP + p0) * NL;
        #pragma unroll
        for (int it = 0; it < EPPT; it++) {
            const int* q = src + (it * ETH + threadIdx.x) * NL;
            #pragma unroll
            for (int l = 0; l < NL; l++) w[it][l] = __ldg(q + l);
        }
    }

    // --- Phase B: stage the batch's dot table (L2-resident source) ---
    {
        const float4* src4 = reinterpret_cast<const float4*>(g_dot + (size_t)b * NE * NL);
        float4* dst4 = reinterpret_cast<float4*>(tab);
        #pragma unroll
        for (int i = threadIdx.x; i < (NE * NL) / 4; i += ETH)   // 2560 float4
            dst4[i] = __ldg(src4 + i);
    }
    __syncthreads();

    // --- Phase C: gather + reduce ---
    #pragma unroll
    for (int it = 0; it < EPPT; it++) {
        float acc = 0.f;
        int cnt = 0;
        #pragma unroll
        for (int l = 0; l < NL; l++) {
            int idx = w[it][l];
            if (idx >= 0) { acc += tab[idx * NL + l]; cnt++; }
        }
        out[(size_t)b * NP + p0 + it * ETH + threadIdx.x] = acc * recip[cnt];
    }
}

// ---------------------------------------------------------------------------
extern "C" void kernel_launch(void* const* d_in, const int* in_sizes, int n_in,
                              void* d_out, int out_size) {
    const float* emb   = (const float*)d_in[0];  // (B, E, D) float32
    const void*  paths = d_in[1];                // (B, P, L) int64 or int32
    const float* ev    = (const float*)d_in[2];  // (L, D) float32
    float* out = (float*)d_out;                  // (B, P) float32

    // 32768 rows, 32 rows/block
    dot_kernel<<<NB * NE / 32, 256>>>(emb, ev, (const int*)paths);

    cudaFuncSetAttribute(enc_kernel, cudaFuncAttributeMaxDynamicSharedMemorySize,
                         ENC_SMEM);
    dim3 grid(EBX, NB);                       // (8, 16) = 128 blocks, one wave
    enc_kernel<<<grid, ETH, ENC_SMEM>>>(paths, out);
}